// round 5
// baseline (speedup 1.0000x reference)
#include <cuda_runtime.h>
#include <math.h>

#define BB 4
#define NN 8192
#define ROWS (BB*NN)     // 32768
#define CIN 64
#define MID 64
#define COUT 128
#define KNB 16
#define TS 2048
#define EPSBN 1e-5f
#define FULLM 0xffffffffu

// ---------------- scratch ----------------
__device__ float4 g_c4[ROWS];                 // (x,y,z,|c|^2)
__device__ int   g_knn[ROWS*KNB];
__device__ float g_X [ROWS*CIN];
__device__ float g_Y1[ROWS*MID];
__device__ float g_Ag[ROWS*MID];
__device__ float g_Ya[ROWS*MID];
__device__ float g_Y2[ROWS*COUT];
__device__ float g_Ps1[256*MID],  g_Pq1[256*MID];
__device__ float g_Psa[256*MID],  g_Pqa[256*MID];
__device__ float g_Ps2[256*COUT], g_Pq2[256*COUT];
__device__ float g_A1[MID],  g_C1[MID];
__device__ float g_Aa[MID],  g_Ca[MID];
__device__ float g_A2[COUT], g_C2[COUT];

// ---------------- prep (3 chunked launches so k_knn is launch #4) ----------------
__global__ void __launch_bounds__(256) k_prep(const float* __restrict__ coords, int off)
{
    const int r = off + blockIdx.x * 256 + threadIdx.x;
    const float x = coords[r*3+0], y = coords[r*3+1], z = coords[r*3+2];
    g_c4[r] = make_float4(x, y, z, x*x + y*y + z*z);
}

// ---------------- kNN: FOUR queries per warp, two list registers ----------------
// regA holds q0's sorted top-16 in lanes 0..15 and q1's in lanes 16..31;
// regB holds q2 / q3 the same way. One LDS.128 + 12 FMA + 1 ballot serves
// 128 query-candidate pairs. Inserts are convergent masked rotates.
__global__ void __launch_bounds__(256) k_knn()
{
    __shared__ float4 tile[TS];   // 32KB
    const int b = blockIdx.y;
    const int warp = threadIdx.x >> 5;
    const int lane = threadIdx.x & 31;
    const float4* cb4 = g_c4 + (size_t)b * NN;

    const int qbase = blockIdx.x * 32 + warp * 4;
    float qx0, qy0, qz0, qx1, qy1, qz1, qx2, qy2, qz2, qx3, qy3, qz3;
    {
        float4 qc;
        qc = cb4[qbase+0]; qx0 = -2.f*qc.x; qy0 = -2.f*qc.y; qz0 = -2.f*qc.z;
        qc = cb4[qbase+1]; qx1 = -2.f*qc.x; qy1 = -2.f*qc.y; qz1 = -2.f*qc.z;
        qc = cb4[qbase+2]; qx2 = -2.f*qc.x; qy2 = -2.f*qc.y; qz2 = -2.f*qc.z;
        qc = cb4[qbase+3]; qx3 = -2.f*qc.x; qy3 = -2.f*qc.y; qz3 = -2.f*qc.z;
    }

    float kdA = 3.0e38f, kdB = 3.0e38f;
    int   kiA = 0,       kiB = 0;
    float kth0 = 3.0e38f, kth1 = 3.0e38f, kth2 = 3.0e38f, kth3 = 3.0e38f;

    for (int t0 = 0; t0 < NN; t0 += TS) {
        __syncthreads();
        for (int i = threadIdx.x; i < TS; i += 256)
            tile[i] = cb4[t0 + i];
        __syncthreads();

#pragma unroll 4
        for (int i = lane; i < TS; i += 32) {
            const float4 c = tile[i];
            const float d0 = fmaf(qx0, c.x, fmaf(qy0, c.y, fmaf(qz0, c.z, c.w)));
            const float d1 = fmaf(qx1, c.x, fmaf(qy1, c.y, fmaf(qz1, c.z, c.w)));
            const float d2 = fmaf(qx2, c.x, fmaf(qy2, c.y, fmaf(qz2, c.z, c.w)));
            const float d3 = fmaf(qx3, c.x, fmaf(qy3, c.y, fmaf(qz3, c.z, c.w)));
            unsigned m = __ballot_sync(FULLM,
                (d0 < kth0) || (d1 < kth1) || (d2 < kth2) || (d3 < kth3));
            while (m) {
                const int src = __ffs(m) - 1; m &= m - 1;
                const float dn0 = __shfl_sync(FULLM, d0, src);
                const float dn1 = __shfl_sync(FULLM, d1, src);
                const float dn2 = __shfl_sync(FULLM, d2, src);
                const float dn3 = __shfl_sync(FULLM, d3, src);
                const int   jn  = t0 + __shfl_sync(FULLM, i, src);
                if (dn0 < kth0) {   // q0 -> regA lanes 0..15
                    const unsigned le = __ballot_sync(FULLM, kdA <= dn0) & 0xffffu;
                    const int pos = __popc(le);
                    const float kdp = __shfl_up_sync(FULLM, kdA, 1);
                    const int   kip = __shfl_up_sync(FULLM, kiA, 1);
                    if (lane == pos)                   { kdA = dn0; kiA = jn; }
                    else if (lane > pos && lane < KNB) { kdA = kdp; kiA = kip; }
                    kth0 = __shfl_sync(FULLM, kdA, 15);
                }
                if (dn1 < kth1) {   // q1 -> regA lanes 16..31
                    const unsigned hi = __ballot_sync(FULLM, kdA <= dn1) & 0xffff0000u;
                    const int pos = 16 + __popc(hi);
                    const float kdp = __shfl_up_sync(FULLM, kdA, 1);
                    const int   kip = __shfl_up_sync(FULLM, kiA, 1);
                    if (lane == pos)     { kdA = dn1; kiA = jn; }
                    else if (lane > pos) { kdA = kdp; kiA = kip; }
                    kth1 = __shfl_sync(FULLM, kdA, 31);
                }
                if (dn2 < kth2) {   // q2 -> regB lanes 0..15
                    const unsigned le = __ballot_sync(FULLM, kdB <= dn2) & 0xffffu;
                    const int pos = __popc(le);
                    const float kdp = __shfl_up_sync(FULLM, kdB, 1);
                    const int   kip = __shfl_up_sync(FULLM, kiB, 1);
                    if (lane == pos)                   { kdB = dn2; kiB = jn; }
                    else if (lane > pos && lane < KNB) { kdB = kdp; kiB = kip; }
                    kth2 = __shfl_sync(FULLM, kdB, 15);
                }
                if (dn3 < kth3) {   // q3 -> regB lanes 16..31
                    const unsigned hi = __ballot_sync(FULLM, kdB <= dn3) & 0xffff0000u;
                    const int pos = 16 + __popc(hi);
                    const float kdp = __shfl_up_sync(FULLM, kdB, 1);
                    const int   kip = __shfl_up_sync(FULLM, kiB, 1);
                    if (lane == pos)     { kdB = dn3; kiB = jn; }
                    else if (lane > pos) { kdB = kdp; kiB = kip; }
                    kth3 = __shfl_sync(FULLM, kdB, 31);
                }
            }
        }
    }

    const int qqA = qbase + (lane >> 4);
    g_knn[((size_t)(b*NN + qqA))*KNB + (lane & 15)] = kiA;
    const int qqB = qbase + 2 + (lane >> 4);
    g_knn[((size_t)(b*NN + qqB))*KNB + (lane & 15)] = kiB;
}

// ---------------- gather + mean: one warp per point ----------------
__global__ void __launch_bounds__(256) k_gather(const float* __restrict__ feats)
{
    const int row  = blockIdx.x * 8 + (threadIdx.x >> 5);
    const int lane = threadIdx.x & 31;
    const int b = row >> 13;
    const float* fb = feats + (size_t)b * NN * CIN;
    const int* ip = g_knn + (size_t)row * KNB;

    float2 acc = make_float2(0.f, 0.f);
#pragma unroll
    for (int m = 0; m < KNB; ++m) {
        const int id = ip[m];
        const float2 v = ((const float2*)(fb + (size_t)id * CIN))[lane];
        acc.x += v.x; acc.y += v.y;
    }
    ((float2*)(g_X + (size_t)row * CIN))[lane] =
        make_float2(acc.x * (1.0f/KNB), acc.y * (1.0f/KNB));
}

// ---------------- warp sum ----------------
__device__ __forceinline__ float warp_sum(float v) {
#pragma unroll
    for (int o = 16; o; o >>= 1) v += __shfl_xor_sync(FULLM, v, o);
    return v;
}

// ---------------- MLP1: channel-split x4 ----------------
__global__ void __launch_bounds__(128) k_mlp1(const float* __restrict__ W,
                                              const float* __restrict__ bias)
{
    __shared__ float Ws[CIN*16];
    __shared__ float wsum[4][16], wsq[4][16];
    const int tid = threadIdx.x;
    const int cg = blockIdx.y;
    for (int i = tid; i < CIN*16; i += 128) {
        const int k = i >> 4, c = i & 15;
        Ws[i] = W[k*MID + cg*16 + c];
    }
    __syncthreads();

    const int r = blockIdx.x * 128 + tid;
    float x[CIN];
    {
        const float4* xp = (const float4*)(g_X + (size_t)r * CIN);
#pragma unroll
        for (int i = 0; i < CIN/4; ++i) {
            float4 v = xp[i];
            x[4*i]=v.x; x[4*i+1]=v.y; x[4*i+2]=v.z; x[4*i+3]=v.w;
        }
    }
    const int warp = tid >> 5, lane = tid & 31;
    float4* yp = (float4*)(g_Y1 + (size_t)r * MID + cg*16);
    const float4* W4 = (const float4*)Ws;
    const float4* b4 = (const float4*)(bias + cg*16);

#pragma unroll
    for (int g = 0; g < 4; ++g) {
        float4 acc = b4[g];
#pragma unroll
        for (int k = 0; k < CIN; ++k) {
            const float4 w = W4[k*4+g];
            acc.x = fmaf(x[k], w.x, acc.x);
            acc.y = fmaf(x[k], w.y, acc.y);
            acc.z = fmaf(x[k], w.z, acc.z);
            acc.w = fmaf(x[k], w.w, acc.w);
        }
        yp[g] = acc;
        const float vs[4] = {acc.x, acc.y, acc.z, acc.w};
#pragma unroll
        for (int u = 0; u < 4; ++u) {
            const float s = warp_sum(vs[u]);
            const float qq = warp_sum(vs[u]*vs[u]);
            if (lane == 0) { wsum[warp][4*g+u] = s; wsq[warp][4*g+u] = qq; }
        }
    }
    __syncthreads();
    if (tid < 16) {
        g_Ps1[blockIdx.x*MID + cg*16 + tid] = wsum[0][tid]+wsum[1][tid]+wsum[2][tid]+wsum[3][tid];
        g_Pq1[blockIdx.x*MID + cg*16 + tid] = wsq [0][tid]+wsq [1][tid]+wsq [2][tid]+wsq [3][tid];
    }
}

// ---------------- BN stats finalize ----------------
__device__ __forceinline__ void stats_mid(const float* Ps, const float* Pq,
                                          const float* g, const float* be,
                                          float* A, float* C)
{
    __shared__ float ss[256], sq[256];
    const int tid = threadIdx.x;
    const int c = tid & (MID-1);
    const int grp = tid >> 6;
    float s = 0.f, q = 0.f;
    const int i0 = grp * 64;
#pragma unroll 4
    for (int i = i0; i < i0 + 64; ++i) { s += Ps[i*MID+c]; q += Pq[i*MID+c]; }
    ss[tid] = s; sq[tid] = q;
    __syncthreads();
    if (tid < MID) {
        s = ss[tid] + ss[tid+64] + ss[tid+128] + ss[tid+192];
        q = sq[tid] + sq[tid+64] + sq[tid+128] + sq[tid+192];
        const float m = s / (float)ROWS;
        const float v = q / (float)ROWS - m*m;
        const float a = g[tid] / sqrtf(v + EPSBN);
        A[tid] = a; C[tid] = be[tid] - m*a;
    }
}
__global__ void k_stats1(const float* __restrict__ g, const float* __restrict__ be)
{ stats_mid(g_Ps1, g_Pq1, g, be, g_A1, g_C1); }
__global__ void k_statsa(const float* __restrict__ g, const float* __restrict__ be)
{ stats_mid(g_Psa, g_Pqa, g, be, g_Aa, g_Ca); }

__global__ void k_stats2(const float* __restrict__ g, const float* __restrict__ be)
{
    __shared__ float ss[512], sq[512];
    const int tid = threadIdx.x;
    const int c = tid & (COUT-1);
    const int grp = tid >> 7;
    float s = 0.f, q = 0.f;
    const int i0 = grp * 64;
#pragma unroll 4
    for (int i = i0; i < i0 + 64; ++i) { s += g_Ps2[i*COUT+c]; q += g_Pq2[i*COUT+c]; }
    ss[tid] = s; sq[tid] = q;
    __syncthreads();
    if (tid < COUT) {
        s = ss[tid] + ss[tid+128] + ss[tid+256] + ss[tid+384];
        q = sq[tid] + sq[tid+128] + sq[tid+256] + sq[tid+384];
        const float m = s / (float)ROWS;
        const float v = q / (float)ROWS - m*m;
        const float a = g[tid] / sqrtf(v + EPSBN);
        g_A2[tid] = a; g_C2[tid] = be[tid] - m*a;
    }
}

// ---------------- MLPa: channel-split x4 ----------------
__global__ void __launch_bounds__(128) k_mlpa(const float* __restrict__ W,
                                              const float* __restrict__ bias)
{
    __shared__ float Ws[MID*16];
    __shared__ float wsum[4][16], wsq[4][16];
    const int tid = threadIdx.x;
    const int cg = blockIdx.y;
    for (int i = tid; i < MID*16; i += 128) {
        const int k = i >> 4, c = i & 15;
        Ws[i] = W[k*MID + cg*16 + c];
    }
    __syncthreads();

    const int r = blockIdx.x * 128 + tid;
    float x[MID];
    {
        const float4* yp = (const float4*)(g_Y1 + (size_t)r * MID);
        float4* ap = (float4*)(g_Ag + (size_t)r * MID);
#pragma unroll
        for (int i = 0; i < MID/4; ++i) {
            float4 v = yp[i];
            float z0 = fmaxf(fmaf(g_A1[4*i+0], v.x, g_C1[4*i+0]), 0.f);
            float z1 = fmaxf(fmaf(g_A1[4*i+1], v.y, g_C1[4*i+1]), 0.f);
            float z2 = fmaxf(fmaf(g_A1[4*i+2], v.z, g_C1[4*i+2]), 0.f);
            float z3 = fmaxf(fmaf(g_A1[4*i+3], v.w, g_C1[4*i+3]), 0.f);
            if (cg == 0) ap[i] = make_float4(z0, z1, z2, z3);
            x[4*i]=z0; x[4*i+1]=z1; x[4*i+2]=z2; x[4*i+3]=z3;
        }
    }
    const int warp = tid >> 5, lane = tid & 31;
    float4* yp = (float4*)(g_Ya + (size_t)r * MID + cg*16);
    const float4* W4 = (const float4*)Ws;
    const float4* b4 = (const float4*)(bias + cg*16);

#pragma unroll
    for (int g = 0; g < 4; ++g) {
        float4 acc = b4[g];
#pragma unroll
        for (int k = 0; k < MID; ++k) {
            const float4 w = W4[k*4+g];
            acc.x = fmaf(x[k], w.x, acc.x);
            acc.y = fmaf(x[k], w.y, acc.y);
            acc.z = fmaf(x[k], w.z, acc.z);
            acc.w = fmaf(x[k], w.w, acc.w);
        }
        yp[g] = acc;
        const float vs[4] = {acc.x, acc.y, acc.z, acc.w};
#pragma unroll
        for (int u = 0; u < 4; ++u) {
            const float s = warp_sum(vs[u]);
            const float qq = warp_sum(vs[u]*vs[u]);
            if (lane == 0) { wsum[warp][4*g+u] = s; wsq[warp][4*g+u] = qq; }
        }
    }
    __syncthreads();
    if (tid < 16) {
        g_Psa[blockIdx.x*MID + cg*16 + tid] = wsum[0][tid]+wsum[1][tid]+wsum[2][tid]+wsum[3][tid];
        g_Pqa[blockIdx.x*MID + cg*16 + tid] = wsq [0][tid]+wsq [1][tid]+wsq [2][tid]+wsq [3][tid];
    }
}

// ---------------- MLP2: channel-split x4 ----------------
__global__ void __launch_bounds__(128) k_mlp2(const float* __restrict__ W,
                                              const float* __restrict__ bias)
{
    __shared__ float Ws[MID*32];
    __shared__ float wsum[4][32], wsq[4][32];
    const int tid = threadIdx.x;
    const int cg = blockIdx.y;
    for (int i = tid; i < MID*32; i += 128) {
        const int k = i >> 5, c = i & 31;
        Ws[i] = W[k*COUT + cg*32 + c];
    }
    __syncthreads();

    const int r = blockIdx.x * 128 + tid;
    float x[MID];
    {
        const float4* yp = (const float4*)(g_Ya + (size_t)r * MID);
        const float4* ap = (const float4*)(g_Ag + (size_t)r * MID);
#pragma unroll
        for (int i = 0; i < MID/4; ++i) {
            float4 y = yp[i];
            float4 a = ap[i];
            float t0 = fmaxf(fmaf(g_Aa[4*i+0], y.x, g_Ca[4*i+0]), 0.f);
            float t1 = fmaxf(fmaf(g_Aa[4*i+1], y.y, g_Ca[4*i+1]), 0.f);
            float t2 = fmaxf(fmaf(g_Aa[4*i+2], y.z, g_Ca[4*i+2]), 0.f);
            float t3 = fmaxf(fmaf(g_Aa[4*i+3], y.w, g_Ca[4*i+3]), 0.f);
            float s0 = 1.0f / (1.0f + expf(-t0));
            float s1 = 1.0f / (1.0f + expf(-t1));
            float s2 = 1.0f / (1.0f + expf(-t2));
            float s3 = 1.0f / (1.0f + expf(-t3));
            x[4*i+0] = fmaf(a.x, s0, a.x);
            x[4*i+1] = fmaf(a.y, s1, a.y);
            x[4*i+2] = fmaf(a.z, s2, a.z);
            x[4*i+3] = fmaf(a.w, s3, a.w);
        }
    }
    const int warp = tid >> 5, lane = tid & 31;
    float4* yp = (float4*)(g_Y2 + (size_t)r * COUT + cg*32);
    const float4* W4 = (const float4*)Ws;
    const float4* b4 = (const float4*)(bias + cg*32);

#pragma unroll
    for (int g = 0; g < 8; ++g) {
        float4 acc = b4[g];
#pragma unroll
        for (int k = 0; k < MID; ++k) {
            const float4 w = W4[k*8+g];
            acc.x = fmaf(x[k], w.x, acc.x);
            acc.y = fmaf(x[k], w.y, acc.y);
            acc.z = fmaf(x[k], w.z, acc.z);
            acc.w = fmaf(x[k], w.w, acc.w);
        }
        yp[g] = acc;
        const float vs[4] = {acc.x, acc.y, acc.z, acc.w};
#pragma unroll
        for (int u = 0; u < 4; ++u) {
            const float s = warp_sum(vs[u]);
            const float qq = warp_sum(vs[u]*vs[u]);
            if (lane == 0) { wsum[warp][4*g+u] = s; wsq[warp][4*g+u] = qq; }
        }
    }
    __syncthreads();
    if (tid < 32) {
        g_Ps2[blockIdx.x*COUT + cg*32 + tid] = wsum[0][tid]+wsum[1][tid]+wsum[2][tid]+wsum[3][tid];
        g_Pq2[blockIdx.x*COUT + cg*32 + tid] = wsq [0][tid]+wsq [1][tid]+wsq [2][tid]+wsq [3][tid];
    }
}

// ---------------- final ----------------
__global__ void __launch_bounds__(256) k_final(float* __restrict__ out)
{
    const int i = blockIdx.x * 256 + threadIdx.x;
    const int c = i & (COUT-1);
    out[i] = fmaxf(fmaf(g_A2[c], g_Y2[i], g_C2[c]), 0.f);
}

// ---------------- launch ----------------
extern "C" void kernel_launch(void* const* d_in, const int* in_sizes, int n_in,
                              void* d_out, int out_size)
{
    const float* coords = (const float*)d_in[0];
    const float* feats  = (const float*)d_in[1];
    const float* W1  = (const float*)d_in[3];
    const float* b1  = (const float*)d_in[4];
    const float* g1  = (const float*)d_in[5];
    const float* be1 = (const float*)d_in[6];
    const float* Wa  = (const float*)d_in[7];
    const float* ba  = (const float*)d_in[8];
    const float* ga  = (const float*)d_in[9];
    const float* bea = (const float*)d_in[10];
    const float* W2  = (const float*)d_in[11];
    const float* b2  = (const float*)d_in[12];
    const float* g2  = (const float*)d_in[13];
    const float* be2 = (const float*)d_in[14];
    float* out = (float*)d_out;

    k_prep  <<<43, 256>>>(coords, 0);
    k_prep  <<<43, 256>>>(coords, 43*256);
    k_prep  <<<42, 256>>>(coords, 86*256);
    k_knn   <<<dim3(NN/32, BB), 256>>>();
    k_gather<<<ROWS/8, 256>>>(feats);
    k_mlp1  <<<dim3(256, 4), 128>>>(W1, b1);
    k_stats1<<<1, 256>>>(g1, be1);
    k_mlpa  <<<dim3(256, 4), 128>>>(Wa, ba);
    k_statsa<<<1, 256>>>(ga, bea);
    k_mlp2  <<<dim3(256, 4), 128>>>(W2, b2);
    k_stats2<<<1, 512>>>(g2, be2);
    k_final <<<(ROWS*COUT)/256, 256>>>(out);
}

// round 6
// speedup vs baseline: 1.2041x; 1.2041x over previous
#include <cuda_runtime.h>
#include <math.h>

#define BB 4
#define NN 8192
#define ROWS (BB*NN)     // 32768
#define CIN 64
#define MID 64
#define COUT 128
#define KNB 16
#define TS 2048
#define EPSBN 1e-5f
#define FULLM 0xffffffffu

// ---------------- scratch ----------------
__device__ float4 g_c4[ROWS];                 // (x,y,z,|c|^2)
__device__ int   g_knn[ROWS*KNB];
__device__ float g_X [ROWS*CIN];
__device__ float g_Y1[ROWS*MID];
__device__ float g_Ag[ROWS*MID];
__device__ float g_Ya[ROWS*MID];
__device__ float g_Y2[ROWS*COUT];
__device__ float g_Ps1[256*MID],  g_Pq1[256*MID];
__device__ float g_Psa[256*MID],  g_Pqa[256*MID];
__device__ float g_Ps2[256*COUT], g_Pq2[256*COUT];
__device__ float g_A1[MID],  g_C1[MID];
__device__ float g_Aa[MID],  g_Ca[MID];
__device__ float g_A2[COUT], g_C2[COUT];

// ---------------- prep ----------------
__global__ void __launch_bounds__(256) k_prep(const float* __restrict__ coords)
{
    const int r = blockIdx.x * 256 + threadIdx.x;
    const float x = coords[r*3+0], y = coords[r*3+1], z = coords[r*3+2];
    g_c4[r] = make_float4(x, y, z, x*x + y*y + z*z);
}

// ---------------- kNN: TWO queries per warp (R4 structure + micro-opts) ----------------
// q0's sorted top-16 lives in lanes 0..15, q1's in lanes 16..31.
// jn computed arithmetically (scan index affine in lane) — no shfl needed.
__global__ void __launch_bounds__(256) k_knn()
{
    __shared__ float4 tile[TS];   // 32KB
    const int b = blockIdx.y;
    const int warp = threadIdx.x >> 5;
    const int lane = threadIdx.x & 31;
    const float4* cb4 = g_c4 + (size_t)b * NN;

    const int q0 = blockIdx.x * 16 + warp * 2;
    const int q1 = q0 + 1;
    const float4 qa = cb4[q0];
    const float4 qb = cb4[q1];
    const float q0x = -2.0f*qa.x, q0y = -2.0f*qa.y, q0z = -2.0f*qa.z;
    const float q1x = -2.0f*qb.x, q1y = -2.0f*qb.y, q1z = -2.0f*qb.z;

    float kd = 3.0e38f;                 // lane's slot of its half's list
    int   ki = 0;
    float kth0 = 3.0e38f, kth1 = 3.0e38f;

    for (int t0 = 0; t0 < NN; t0 += TS) {
        __syncthreads();
        for (int i = threadIdx.x; i < TS; i += 256)
            tile[i] = cb4[t0 + i];
        __syncthreads();

#pragma unroll 4
        for (int base = 0; base < TS; base += 32) {
            const float4 c = tile[base + lane];
            const float d0 = fmaf(q0x, c.x, fmaf(q0y, c.y, fmaf(q0z, c.z, c.w)));
            const float d1 = fmaf(q1x, c.x, fmaf(q1y, c.y, fmaf(q1z, c.z, c.w)));
            unsigned m = __ballot_sync(FULLM, (d0 < kth0) || (d1 < kth1));
            while (m) {
                const int src = __ffs(m) - 1; m &= m - 1;
                const float dn0 = __shfl_sync(FULLM, d0, src);
                const float dn1 = __shfl_sync(FULLM, d1, src);
                const int   jn  = t0 + base + src;
                if (dn0 < kth0) {   // warp-uniform branch
                    const unsigned le = __ballot_sync(FULLM, kd <= dn0) & 0xffffu;
                    const int pos = __popc(le);
                    const float kdp = __shfl_up_sync(FULLM, kd, 1);
                    const int   kip = __shfl_up_sync(FULLM, ki, 1);
                    if (lane == pos)                   { kd = dn0; ki = jn; }
                    else if (lane > pos && lane < KNB) { kd = kdp; ki = kip; }
                    kth0 = __shfl_sync(FULLM, kd, 15);
                }
                if (dn1 < kth1) {   // warp-uniform branch
                    const unsigned hi = __ballot_sync(FULLM, kd <= dn1) & 0xffff0000u;
                    const int pos = 16 + __popc(hi);
                    const float kdp = __shfl_up_sync(FULLM, kd, 1);
                    const int   kip = __shfl_up_sync(FULLM, ki, 1);
                    if (lane == pos)     { kd = dn1; ki = jn; }
                    else if (lane > pos) { kd = kdp; ki = kip; }
                    kth1 = __shfl_sync(FULLM, kd, 31);
                }
            }
        }
    }

    const int qq = q0 + (lane >> 4);
    g_knn[((size_t)(b*NN + qq))*KNB + (lane & 15)] = ki;
}

// ---------------- gather + mean: one warp per point ----------------
__global__ void __launch_bounds__(256) k_gather(const float* __restrict__ feats)
{
    const int row  = blockIdx.x * 8 + (threadIdx.x >> 5);
    const int lane = threadIdx.x & 31;
    const int b = row >> 13;
    const float* fb = feats + (size_t)b * NN * CIN;
    const int* ip = g_knn + (size_t)row * KNB;

    float2 acc = make_float2(0.f, 0.f);
#pragma unroll
    for (int m = 0; m < KNB; ++m) {
        const int id = ip[m];
        const float2 v = ((const float2*)(fb + (size_t)id * CIN))[lane];
        acc.x += v.x; acc.y += v.y;
    }
    ((float2*)(g_X + (size_t)row * CIN))[lane] =
        make_float2(acc.x * (1.0f/KNB), acc.y * (1.0f/KNB));
}

// ---------------- warp sum ----------------
__device__ __forceinline__ float warp_sum(float v) {
#pragma unroll
    for (int o = 16; o; o >>= 1) v += __shfl_xor_sync(FULLM, v, o);
    return v;
}

// ---------------- MLP1: channel-split x4 ----------------
__global__ void __launch_bounds__(128) k_mlp1(const float* __restrict__ W,
                                              const float* __restrict__ bias)
{
    __shared__ float Ws[CIN*16];
    __shared__ float wsum[4][16], wsq[4][16];
    const int tid = threadIdx.x;
    const int cg = blockIdx.y;
    for (int i = tid; i < CIN*16; i += 128) {
        const int k = i >> 4, c = i & 15;
        Ws[i] = W[k*MID + cg*16 + c];
    }
    __syncthreads();

    const int r = blockIdx.x * 128 + tid;
    float x[CIN];
    {
        const float4* xp = (const float4*)(g_X + (size_t)r * CIN);
#pragma unroll
        for (int i = 0; i < CIN/4; ++i) {
            float4 v = xp[i];
            x[4*i]=v.x; x[4*i+1]=v.y; x[4*i+2]=v.z; x[4*i+3]=v.w;
        }
    }
    const int warp = tid >> 5, lane = tid & 31;
    float4* yp = (float4*)(g_Y1 + (size_t)r * MID + cg*16);
    const float4* W4 = (const float4*)Ws;
    const float4* b4 = (const float4*)(bias + cg*16);

#pragma unroll
    for (int g = 0; g < 4; ++g) {
        float4 acc = b4[g];
#pragma unroll
        for (int k = 0; k < CIN; ++k) {
            const float4 w = W4[k*4+g];
            acc.x = fmaf(x[k], w.x, acc.x);
            acc.y = fmaf(x[k], w.y, acc.y);
            acc.z = fmaf(x[k], w.z, acc.z);
            acc.w = fmaf(x[k], w.w, acc.w);
        }
        yp[g] = acc;
        const float vs[4] = {acc.x, acc.y, acc.z, acc.w};
#pragma unroll
        for (int u = 0; u < 4; ++u) {
            const float s = warp_sum(vs[u]);
            const float qq = warp_sum(vs[u]*vs[u]);
            if (lane == 0) { wsum[warp][4*g+u] = s; wsq[warp][4*g+u] = qq; }
        }
    }
    __syncthreads();
    if (tid < 16) {
        g_Ps1[blockIdx.x*MID + cg*16 + tid] = wsum[0][tid]+wsum[1][tid]+wsum[2][tid]+wsum[3][tid];
        g_Pq1[blockIdx.x*MID + cg*16 + tid] = wsq [0][tid]+wsq [1][tid]+wsq [2][tid]+wsq [3][tid];
    }
}

// ---------------- BN stats finalize ----------------
__device__ __forceinline__ void stats_mid(const float* Ps, const float* Pq,
                                          const float* g, const float* be,
                                          float* A, float* C)
{
    __shared__ float ss[256], sq[256];
    const int tid = threadIdx.x;
    const int c = tid & (MID-1);
    const int grp = tid >> 6;
    float s = 0.f, q = 0.f;
    const int i0 = grp * 64;
#pragma unroll 4
    for (int i = i0; i < i0 + 64; ++i) { s += Ps[i*MID+c]; q += Pq[i*MID+c]; }
    ss[tid] = s; sq[tid] = q;
    __syncthreads();
    if (tid < MID) {
        s = ss[tid] + ss[tid+64] + ss[tid+128] + ss[tid+192];
        q = sq[tid] + sq[tid+64] + sq[tid+128] + sq[tid+192];
        const float m = s / (float)ROWS;
        const float v = q / (float)ROWS - m*m;
        const float a = g[tid] / sqrtf(v + EPSBN);
        A[tid] = a; C[tid] = be[tid] - m*a;
    }
}
__global__ void k_stats1(const float* __restrict__ g, const float* __restrict__ be)
{ stats_mid(g_Ps1, g_Pq1, g, be, g_A1, g_C1); }
__global__ void k_statsa(const float* __restrict__ g, const float* __restrict__ be)
{ stats_mid(g_Psa, g_Pqa, g, be, g_Aa, g_Ca); }

__global__ void k_stats2(const float* __restrict__ g, const float* __restrict__ be)
{
    __shared__ float ss[512], sq[512];
    const int tid = threadIdx.x;
    const int c = tid & (COUT-1);
    const int grp = tid >> 7;
    float s = 0.f, q = 0.f;
    const int i0 = grp * 64;
#pragma unroll 4
    for (int i = i0; i < i0 + 64; ++i) { s += g_Ps2[i*COUT+c]; q += g_Pq2[i*COUT+c]; }
    ss[tid] = s; sq[tid] = q;
    __syncthreads();
    if (tid < COUT) {
        s = ss[tid] + ss[tid+128] + ss[tid+256] + ss[tid+384];
        q = sq[tid] + sq[tid+128] + sq[tid+256] + sq[tid+384];
        const float m = s / (float)ROWS;
        const float v = q / (float)ROWS - m*m;
        const float a = g[tid] / sqrtf(v + EPSBN);
        g_A2[tid] = a; g_C2[tid] = be[tid] - m*a;
    }
}

// ---------------- MLPa: channel-split x4 ----------------
__global__ void __launch_bounds__(128) k_mlpa(const float* __restrict__ W,
                                              const float* __restrict__ bias)
{
    __shared__ float Ws[MID*16];
    __shared__ float wsum[4][16], wsq[4][16];
    const int tid = threadIdx.x;
    const int cg = blockIdx.y;
    for (int i = tid; i < MID*16; i += 128) {
        const int k = i >> 4, c = i & 15;
        Ws[i] = W[k*MID + cg*16 + c];
    }
    __syncthreads();

    const int r = blockIdx.x * 128 + tid;
    float x[MID];
    {
        const float4* yp = (const float4*)(g_Y1 + (size_t)r * MID);
        float4* ap = (float4*)(g_Ag + (size_t)r * MID);
#pragma unroll
        for (int i = 0; i < MID/4; ++i) {
            float4 v = yp[i];
            float z0 = fmaxf(fmaf(g_A1[4*i+0], v.x, g_C1[4*i+0]), 0.f);
            float z1 = fmaxf(fmaf(g_A1[4*i+1], v.y, g_C1[4*i+1]), 0.f);
            float z2 = fmaxf(fmaf(g_A1[4*i+2], v.z, g_C1[4*i+2]), 0.f);
            float z3 = fmaxf(fmaf(g_A1[4*i+3], v.w, g_C1[4*i+3]), 0.f);
            if (cg == 0) ap[i] = make_float4(z0, z1, z2, z3);
            x[4*i]=z0; x[4*i+1]=z1; x[4*i+2]=z2; x[4*i+3]=z3;
        }
    }
    const int warp = tid >> 5, lane = tid & 31;
    float4* yp = (float4*)(g_Ya + (size_t)r * MID + cg*16);
    const float4* W4 = (const float4*)Ws;
    const float4* b4 = (const float4*)(bias + cg*16);

#pragma unroll
    for (int g = 0; g < 4; ++g) {
        float4 acc = b4[g];
#pragma unroll
        for (int k = 0; k < MID; ++k) {
            const float4 w = W4[k*4+g];
            acc.x = fmaf(x[k], w.x, acc.x);
            acc.y = fmaf(x[k], w.y, acc.y);
            acc.z = fmaf(x[k], w.z, acc.z);
            acc.w = fmaf(x[k], w.w, acc.w);
        }
        yp[g] = acc;
        const float vs[4] = {acc.x, acc.y, acc.z, acc.w};
#pragma unroll
        for (int u = 0; u < 4; ++u) {
            const float s = warp_sum(vs[u]);
            const float qq = warp_sum(vs[u]*vs[u]);
            if (lane == 0) { wsum[warp][4*g+u] = s; wsq[warp][4*g+u] = qq; }
        }
    }
    __syncthreads();
    if (tid < 16) {
        g_Psa[blockIdx.x*MID + cg*16 + tid] = wsum[0][tid]+wsum[1][tid]+wsum[2][tid]+wsum[3][tid];
        g_Pqa[blockIdx.x*MID + cg*16 + tid] = wsq [0][tid]+wsq [1][tid]+wsq [2][tid]+wsq [3][tid];
    }
}

// ---------------- MLP2: channel-split x4 ----------------
__global__ void __launch_bounds__(128) k_mlp2(const float* __restrict__ W,
                                              const float* __restrict__ bias)
{
    __shared__ float Ws[MID*32];
    __shared__ float wsum[4][32], wsq[4][32];
    const int tid = threadIdx.x;
    const int cg = blockIdx.y;
    for (int i = tid; i < MID*32; i += 128) {
        const int k = i >> 5, c = i & 31;
        Ws[i] = W[k*COUT + cg*32 + c];
    }
    __syncthreads();

    const int r = blockIdx.x * 128 + tid;
    float x[MID];
    {
        const float4* yp = (const float4*)(g_Ya + (size_t)r * MID);
        const float4* ap = (const float4*)(g_Ag + (size_t)r * MID);
#pragma unroll
        for (int i = 0; i < MID/4; ++i) {
            float4 y = yp[i];
            float4 a = ap[i];
            float t0 = fmaxf(fmaf(g_Aa[4*i+0], y.x, g_Ca[4*i+0]), 0.f);
            float t1 = fmaxf(fmaf(g_Aa[4*i+1], y.y, g_Ca[4*i+1]), 0.f);
            float t2 = fmaxf(fmaf(g_Aa[4*i+2], y.z, g_Ca[4*i+2]), 0.f);
            float t3 = fmaxf(fmaf(g_Aa[4*i+3], y.w, g_Ca[4*i+3]), 0.f);
            float s0 = 1.0f / (1.0f + expf(-t0));
            float s1 = 1.0f / (1.0f + expf(-t1));
            float s2 = 1.0f / (1.0f + expf(-t2));
            float s3 = 1.0f / (1.0f + expf(-t3));
            x[4*i+0] = fmaf(a.x, s0, a.x);
            x[4*i+1] = fmaf(a.y, s1, a.y);
            x[4*i+2] = fmaf(a.z, s2, a.z);
            x[4*i+3] = fmaf(a.w, s3, a.w);
        }
    }
    const int warp = tid >> 5, lane = tid & 31;
    float4* yp = (float4*)(g_Y2 + (size_t)r * COUT + cg*32);
    const float4* W4 = (const float4*)Ws;
    const float4* b4 = (const float4*)(bias + cg*32);

#pragma unroll
    for (int g = 0; g < 8; ++g) {
        float4 acc = b4[g];
#pragma unroll
        for (int k = 0; k < MID; ++k) {
            const float4 w = W4[k*8+g];
            acc.x = fmaf(x[k], w.x, acc.x);
            acc.y = fmaf(x[k], w.y, acc.y);
            acc.z = fmaf(x[k], w.z, acc.z);
            acc.w = fmaf(x[k], w.w, acc.w);
        }
        yp[g] = acc;
        const float vs[4] = {acc.x, acc.y, acc.z, acc.w};
#pragma unroll
        for (int u = 0; u < 4; ++u) {
            const float s = warp_sum(vs[u]);
            const float qq = warp_sum(vs[u]*vs[u]);
            if (lane == 0) { wsum[warp][4*g+u] = s; wsq[warp][4*g+u] = qq; }
        }
    }
    __syncthreads();
    if (tid < 32) {
        g_Ps2[blockIdx.x*COUT + cg*32 + tid] = wsum[0][tid]+wsum[1][tid]+wsum[2][tid]+wsum[3][tid];
        g_Pq2[blockIdx.x*COUT + cg*32 + tid] = wsq [0][tid]+wsq [1][tid]+wsq [2][tid]+wsq [3][tid];
    }
}

// ---------------- final ----------------
__global__ void __launch_bounds__(256) k_final(float* __restrict__ out)
{
    const int i = blockIdx.x * 256 + threadIdx.x;
    const int c = i & (COUT-1);
    out[i] = fmaxf(fmaf(g_A2[c], g_Y2[i], g_C2[c]), 0.f);
}

// ---------------- launch ----------------
extern "C" void kernel_launch(void* const* d_in, const int* in_sizes, int n_in,
                              void* d_out, int out_size)
{
    const float* coords = (const float*)d_in[0];
    const float* feats  = (const float*)d_in[1];
    const float* W1  = (const float*)d_in[3];
    const float* b1  = (const float*)d_in[4];
    const float* g1  = (const float*)d_in[5];
    const float* be1 = (const float*)d_in[6];
    const float* Wa  = (const float*)d_in[7];
    const float* ba  = (const float*)d_in[8];
    const float* ga  = (const float*)d_in[9];
    const float* bea = (const float*)d_in[10];
    const float* W2  = (const float*)d_in[11];
    const float* b2  = (const float*)d_in[12];
    const float* g2  = (const float*)d_in[13];
    const float* be2 = (const float*)d_in[14];
    float* out = (float*)d_out;

    k_prep  <<<ROWS/256, 256>>>(coords);
    k_knn   <<<dim3(NN/16, BB), 256>>>();
    k_gather<<<ROWS/8, 256>>>(feats);
    k_mlp1  <<<dim3(256, 4), 128>>>(W1, b1);   // launch #4 -> profiled
    k_stats1<<<1, 256>>>(g1, be1);
    k_mlpa  <<<dim3(256, 4), 128>>>(Wa, ba);
    k_statsa<<<1, 256>>>(ga, bea);
    k_mlp2  <<<dim3(256, 4), 128>>>(W2, b2);
    k_stats2<<<1, 512>>>(g2, be2);
    k_final <<<(ROWS*COUT)/256, 256>>>(out);
}

// round 9
// speedup vs baseline: 1.2728x; 1.0570x over previous
#include <cuda_runtime.h>
#include <cstdint>
#include <math.h>

#define BB 4
#define NN 8192
#define ROWS (BB*NN)     // 32768
#define CIN 64
#define MID 64
#define COUT 128
#define KNB 16
#define TS 1024
#define NTILE (NN/TS)    // 8
#define EPSBN 1e-5f
#define FULLM 0xffffffffu

// ---------------- scratch ----------------
__device__ float4 g_c4[ROWS];                 // (x,y,z,|c|^2)
__device__ int   g_knn[ROWS*KNB];
__device__ float g_X [ROWS*CIN];
__device__ float g_Y1[ROWS*MID];
__device__ float g_Ag[ROWS*MID];
__device__ float g_Ya[ROWS*MID];
__device__ float g_Y2[ROWS*COUT];
__device__ float g_Ps1[256*MID],  g_Pq1[256*MID];
__device__ float g_Psa[256*MID],  g_Pqa[256*MID];
__device__ float g_Ps2[256*COUT], g_Pq2[256*COUT];
__device__ float g_A1[MID],  g_C1[MID];
__device__ float g_Aa[MID],  g_Ca[MID];
__device__ float g_A2[COUT], g_C2[COUT];

// ---------------- prep ----------------
__global__ void __launch_bounds__(256) k_prep(const float* __restrict__ coords)
{
    const int r = blockIdx.x * 256 + threadIdx.x;
    const float x = coords[r*3+0], y = coords[r*3+1], z = coords[r*3+2];
    g_c4[r] = make_float4(x, y, z, x*x + y*y + z*z);
}

// ---------------- mbarrier helpers ----------------
__device__ __forceinline__ void mbar_init(uint32_t mbar, unsigned count) {
    asm volatile("mbarrier.init.shared.b64 [%0], %1;" :: "r"(mbar), "r"(count));
}
__device__ __forceinline__ void mbar_expect_tx(uint32_t mbar, unsigned bytes) {
    asm volatile("mbarrier.arrive.expect_tx.shared.b64 _, [%0], %1;"
                 :: "r"(mbar), "r"(bytes) : "memory");
}
__device__ __forceinline__ void bulk_g2s(uint32_t dst, const void* src,
                                         unsigned bytes, uint32_t mbar) {
    asm volatile("cp.async.bulk.shared::cta.global.mbarrier::complete_tx::bytes "
                 "[%0], [%1], %2, [%3];"
                 :: "r"(dst), "l"(src), "r"(bytes), "r"(mbar) : "memory");
}
__device__ __forceinline__ void mbar_wait(uint32_t mbar, unsigned phase) {
    asm volatile(
        "{\n\t"
        ".reg .pred P;\n\t"
        "WAIT_%=:\n\t"
        "mbarrier.try_wait.parity.shared.b64 P, [%0], %1;\n\t"
        "@!P bra WAIT_%=;\n\t"
        "}" :: "r"(mbar), "r"(phase) : "memory");
}

// ---------------- kNN: TWO queries per warp + bulk-async double-buffered tiles ------
__global__ void __launch_bounds__(256) k_knn()
{
    __shared__ __align__(16) float4 tile[2][TS];           // 32KB
    __shared__ __align__(8)  unsigned long long mbar[2];
    const int b = blockIdx.y;
    const int warp = threadIdx.x >> 5;
    const int lane = threadIdx.x & 31;
    const int tid = threadIdx.x;
    const float4* cb4 = g_c4 + (size_t)b * NN;

    const uint32_t mb0 = (uint32_t)__cvta_generic_to_shared(&mbar[0]);
    const uint32_t mb1 = (uint32_t)__cvta_generic_to_shared(&mbar[1]);
    const uint32_t td0 = (uint32_t)__cvta_generic_to_shared(&tile[0][0]);
    const uint32_t td1 = (uint32_t)__cvta_generic_to_shared(&tile[1][0]);

    if (tid == 0) {
        mbar_init(mb0, 1);
        mbar_init(mb1, 1);
        asm volatile("fence.proxy.async.shared::cta;" ::: "memory");
    }
    __syncthreads();
    if (tid == 0) {                       // kick off tile 0
        mbar_expect_tx(mb0, TS*16);
        bulk_g2s(td0, cb4, TS*16, mb0);
    }

    const int q0 = blockIdx.x * 16 + warp * 2;
    const int q1 = q0 + 1;
    const float4 qa = cb4[q0];
    const float4 qb = cb4[q1];
    const float q0x = -2.0f*qa.x, q0y = -2.0f*qa.y, q0z = -2.0f*qa.z;
    const float q1x = -2.0f*qb.x, q1y = -2.0f*qb.y, q1z = -2.0f*qb.z;

    float kd = 3.0e38f;                 // lane's slot of its half's list
    int   ki = 0;
    float kth0 = 3.0e38f, kth1 = 3.0e38f;

    for (int t = 0; t < NTILE; ++t) {
        const int buf = t & 1;
        mbar_wait(buf ? mb1 : mb0, (t >> 1) & 1);
        __syncthreads();                  // all warps past previous use of this buffer
        if (t + 1 < NTILE && tid == 0) {  // prefetch next into other buffer
            mbar_expect_tx(buf ? mb0 : mb1, TS*16);
            bulk_g2s(buf ? td0 : td1, cb4 + (t+1)*TS, TS*16, buf ? mb0 : mb1);
        }
        const float4* tp = tile[buf];
        const int t0 = t * TS;

#pragma unroll 4
        for (int base = 0; base < TS; base += 32) {
            const float4 c = tp[base + lane];
            const float d0 = fmaf(q0x, c.x, fmaf(q0y, c.y, fmaf(q0z, c.z, c.w)));
            const float d1 = fmaf(q1x, c.x, fmaf(q1y, c.y, fmaf(q1z, c.z, c.w)));
            unsigned m = __ballot_sync(FULLM, (d0 < kth0) || (d1 < kth1));
            while (m) {
                const int src = __ffs(m) - 1; m &= m - 1;
                const float dn0 = __shfl_sync(FULLM, d0, src);
                const float dn1 = __shfl_sync(FULLM, d1, src);
                const int   jn  = t0 + base + src;
                if (dn0 < kth0) {   // warp-uniform branch
                    const unsigned le = __ballot_sync(FULLM, kd <= dn0) & 0xffffu;
                    const int pos = __popc(le);
                    const float kdp = __shfl_up_sync(FULLM, kd, 1);
                    const int   kip = __shfl_up_sync(FULLM, ki, 1);
                    if (lane == pos)                   { kd = dn0; ki = jn; }
                    else if (lane > pos && lane < KNB) { kd = kdp; ki = kip; }
                    kth0 = __shfl_sync(FULLM, kd, 15);
                }
                if (dn1 < kth1) {   // warp-uniform branch
                    const unsigned hi = __ballot_sync(FULLM, kd <= dn1) & 0xffff0000u;
                    const int pos = 16 + __popc(hi);
                    const float kdp = __shfl_up_sync(FULLM, kd, 1);
                    const int   kip = __shfl_up_sync(FULLM, ki, 1);
                    if (lane == pos)     { kd = dn1; ki = jn; }
                    else if (lane > pos) { kd = kdp; ki = kip; }
                    kth1 = __shfl_sync(FULLM, kd, 31);
                }
            }
        }
    }

    const int qq = q0 + (lane >> 4);
    g_knn[((size_t)(b*NN + qq))*KNB + (lane & 15)] = ki;
}

// ---------------- gather + mean: one warp per point ----------------
__global__ void __launch_bounds__(256) k_gather(const float* __restrict__ feats)
{
    const int row  = blockIdx.x * 8 + (threadIdx.x >> 5);
    const int lane = threadIdx.x & 31;
    const int b = row >> 13;
    const float* fb = feats + (size_t)b * NN * CIN;
    const int* ip = g_knn + (size_t)row * KNB;

    float2 acc = make_float2(0.f, 0.f);
#pragma unroll
    for (int m = 0; m < KNB; ++m) {
        const int id = ip[m];
        const float2 v = ((const float2*)(fb + (size_t)id * CIN))[lane];
        acc.x += v.x; acc.y += v.y;
    }
    ((float2*)(g_X + (size_t)row * CIN))[lane] =
        make_float2(acc.x * (1.0f/KNB), acc.y * (1.0f/KNB));
}

// ---------------- warp sum ----------------
__device__ __forceinline__ float warp_sum(float v) {
#pragma unroll
    for (int o = 16; o; o >>= 1) v += __shfl_xor_sync(FULLM, v, o);
    return v;
}

// ---------------- MLP1: channel-split x4, chunked x (low regs) ----------------
__global__ void __launch_bounds__(128) k_mlp1(const float* __restrict__ W,
                                              const float* __restrict__ bias)
{
    __shared__ float Ws[CIN*16];
    __shared__ float wsum[4][16], wsq[4][16];
    const int tid = threadIdx.x;
    const int cg = blockIdx.y;
    for (int i = tid; i < CIN*16; i += 128) {
        const int k = i >> 4, c = i & 15;
        Ws[i] = W[k*MID + cg*16 + c];
    }
    __syncthreads();

    const int r = blockIdx.x * 128 + tid;
    const float4* xp = (const float4*)(g_X + (size_t)r * CIN);
    const float4* W4 = (const float4*)Ws;               // W4[k*4+g]
    const float4* b4 = (const float4*)(bias + cg*16);

    float4 acc[4];
#pragma unroll
    for (int g = 0; g < 4; ++g) acc[g] = b4[g];

#pragma unroll
    for (int kk = 0; kk < CIN/16; ++kk) {
        float xc[16];
#pragma unroll
        for (int u = 0; u < 4; ++u) {
            const float4 v = xp[kk*4+u];
            xc[4*u]=v.x; xc[4*u+1]=v.y; xc[4*u+2]=v.z; xc[4*u+3]=v.w;
        }
#pragma unroll
        for (int j = 0; j < 16; ++j) {
            const int k = kk*16 + j;
            const float xs = xc[j];
#pragma unroll
            for (int g = 0; g < 4; ++g) {
                const float4 w = W4[k*4+g];
                acc[g].x = fmaf(xs, w.x, acc[g].x);
                acc[g].y = fmaf(xs, w.y, acc[g].y);
                acc[g].z = fmaf(xs, w.z, acc[g].z);
                acc[g].w = fmaf(xs, w.w, acc[g].w);
            }
        }
    }

    const int warp = tid >> 5, lane = tid & 31;
    float4* yp = (float4*)(g_Y1 + (size_t)r * MID + cg*16);
#pragma unroll
    for (int g = 0; g < 4; ++g) {
        yp[g] = acc[g];
        const float vs[4] = {acc[g].x, acc[g].y, acc[g].z, acc[g].w};
#pragma unroll
        for (int u = 0; u < 4; ++u) {
            const float s = warp_sum(vs[u]);
            const float qq = warp_sum(vs[u]*vs[u]);
            if (lane == 0) { wsum[warp][4*g+u] = s; wsq[warp][4*g+u] = qq; }
        }
    }
    __syncthreads();
    if (tid < 16) {
        g_Ps1[blockIdx.x*MID + cg*16 + tid] = wsum[0][tid]+wsum[1][tid]+wsum[2][tid]+wsum[3][tid];
        g_Pq1[blockIdx.x*MID + cg*16 + tid] = wsq [0][tid]+wsq [1][tid]+wsq [2][tid]+wsq [3][tid];
    }
}

// ---------------- BN stats finalize ----------------
__device__ __forceinline__ void stats_mid(const float* Ps, const float* Pq,
                                          const float* g, const float* be,
                                          float* A, float* C)
{
    __shared__ float ss[256], sq[256];
    const int tid = threadIdx.x;
    const int c = tid & (MID-1);
    const int grp = tid >> 6;
    float s = 0.f, q = 0.f;
    const int i0 = grp * 64;
#pragma unroll 4
    for (int i = i0; i < i0 + 64; ++i) { s += Ps[i*MID+c]; q += Pq[i*MID+c]; }
    ss[tid] = s; sq[tid] = q;
    __syncthreads();
    if (tid < MID) {
        s = ss[tid] + ss[tid+64] + ss[tid+128] + ss[tid+192];
        q = sq[tid] + sq[tid+64] + sq[tid+128] + sq[tid+192];
        const float m = s / (float)ROWS;
        const float v = q / (float)ROWS - m*m;
        const float a = g[tid] / sqrtf(v + EPSBN);
        A[tid] = a; C[tid] = be[tid] - m*a;
    }
}
__global__ void k_stats1(const float* __restrict__ g, const float* __restrict__ be)
{ stats_mid(g_Ps1, g_Pq1, g, be, g_A1, g_C1); }
__global__ void k_statsa(const float* __restrict__ g, const float* __restrict__ be)
{ stats_mid(g_Psa, g_Pqa, g, be, g_Aa, g_Ca); }

__global__ void k_stats2(const float* __restrict__ g, const float* __restrict__ be)
{
    __shared__ float ss[512], sq[512];
    const int tid = threadIdx.x;
    const int c = tid & (COUT-1);
    const int grp = tid >> 7;
    float s = 0.f, q = 0.f;
    const int i0 = grp * 64;
#pragma unroll 4
    for (int i = i0; i < i0 + 64; ++i) { s += g_Ps2[i*COUT+c]; q += g_Pq2[i*COUT+c]; }
    ss[tid] = s; sq[tid] = q;
    __syncthreads();
    if (tid < COUT) {
        s = ss[tid] + ss[tid+128] + ss[tid+256] + ss[tid+384];
        q = sq[tid] + sq[tid+128] + sq[tid+256] + sq[tid+384];
        const float m = s / (float)ROWS;
        const float v = q / (float)ROWS - m*m;
        const float a = g[tid] / sqrtf(v + EPSBN);
        g_A2[tid] = a; g_C2[tid] = be[tid] - m*a;
    }
}

// ---------------- MLPa: channel-split x4, chunked x ----------------
__global__ void __launch_bounds__(128) k_mlpa(const float* __restrict__ W,
                                              const float* __restrict__ bias)
{
    __shared__ float Ws[MID*16];
    __shared__ float wsum[4][16], wsq[4][16];
    const int tid = threadIdx.x;
    const int cg = blockIdx.y;
    for (int i = tid; i < MID*16; i += 128) {
        const int k = i >> 4, c = i & 15;
        Ws[i] = W[k*MID + cg*16 + c];
    }
    __syncthreads();

    const int r = blockIdx.x * 128 + tid;
    const float4* yin = (const float4*)(g_Y1 + (size_t)r * MID);
    float4* ap = (float4*)(g_Ag + (size_t)r * MID);
    const float4* W4 = (const float4*)Ws;
    const float4* b4 = (const float4*)(bias + cg*16);

    float4 acc[4];
#pragma unroll
    for (int g = 0; g < 4; ++g) acc[g] = b4[g];

#pragma unroll
    for (int kk = 0; kk < MID/16; ++kk) {
        float xc[16];
#pragma unroll
        for (int u = 0; u < 4; ++u) {
            const int i = kk*4 + u;
            const float4 v = yin[i];
            float z0 = fmaxf(fmaf(g_A1[4*i+0], v.x, g_C1[4*i+0]), 0.f);
            float z1 = fmaxf(fmaf(g_A1[4*i+1], v.y, g_C1[4*i+1]), 0.f);
            float z2 = fmaxf(fmaf(g_A1[4*i+2], v.z, g_C1[4*i+2]), 0.f);
            float z3 = fmaxf(fmaf(g_A1[4*i+3], v.w, g_C1[4*i+3]), 0.f);
            if (cg == 0) ap[i] = make_float4(z0, z1, z2, z3);
            xc[4*u]=z0; xc[4*u+1]=z1; xc[4*u+2]=z2; xc[4*u+3]=z3;
        }
#pragma unroll
        for (int j = 0; j < 16; ++j) {
            const int k = kk*16 + j;
            const float xs = xc[j];
#pragma unroll
            for (int g = 0; g < 4; ++g) {
                const float4 w = W4[k*4+g];
                acc[g].x = fmaf(xs, w.x, acc[g].x);
                acc[g].y = fmaf(xs, w.y, acc[g].y);
                acc[g].z = fmaf(xs, w.z, acc[g].z);
                acc[g].w = fmaf(xs, w.w, acc[g].w);
            }
        }
    }

    const int warp = tid >> 5, lane = tid & 31;
    float4* yp = (float4*)(g_Ya + (size_t)r * MID + cg*16);
#pragma unroll
    for (int g = 0; g < 4; ++g) {
        yp[g] = acc[g];
        const float vs[4] = {acc[g].x, acc[g].y, acc[g].z, acc[g].w};
#pragma unroll
        for (int u = 0; u < 4; ++u) {
            const float s = warp_sum(vs[u]);
            const float qq = warp_sum(vs[u]*vs[u]);
            if (lane == 0) { wsum[warp][4*g+u] = s; wsq[warp][4*g+u] = qq; }
        }
    }
    __syncthreads();
    if (tid < 16) {
        g_Psa[blockIdx.x*MID + cg*16 + tid] = wsum[0][tid]+wsum[1][tid]+wsum[2][tid]+wsum[3][tid];
        g_Pqa[blockIdx.x*MID + cg*16 + tid] = wsq [0][tid]+wsq [1][tid]+wsq [2][tid]+wsq [3][tid];
    }
}

// ---------------- MLP2: channel-split x4, chunked x ----------------
__global__ void __launch_bounds__(128) k_mlp2(const float* __restrict__ W,
                                              const float* __restrict__ bias)
{
    __shared__ float Ws[MID*32];
    __shared__ float wsum[4][32], wsq[4][32];
    const int tid = threadIdx.x;
    const int cg = blockIdx.y;
    for (int i = tid; i < MID*32; i += 128) {
        const int k = i >> 5, c = i & 31;
        Ws[i] = W[k*COUT + cg*32 + c];
    }
    __syncthreads();

    const int r = blockIdx.x * 128 + tid;
    const float4* yin = (const float4*)(g_Ya + (size_t)r * MID);
    const float4* ain = (const float4*)(g_Ag + (size_t)r * MID);
    const float4* W4 = (const float4*)Ws;               // W4[k*8+g]
    const float4* b4 = (const float4*)(bias + cg*32);

    float4 acc[8];
#pragma unroll
    for (int g = 0; g < 8; ++g) acc[g] = b4[g];

#pragma unroll
    for (int kk = 0; kk < MID/16; ++kk) {
        float xc[16];
#pragma unroll
        for (int u = 0; u < 4; ++u) {
            const int i = kk*4 + u;
            const float4 y = yin[i];
            const float4 a = ain[i];
            float t0 = fmaxf(fmaf(g_Aa[4*i+0], y.x, g_Ca[4*i+0]), 0.f);
            float t1 = fmaxf(fmaf(g_Aa[4*i+1], y.y, g_Ca[4*i+1]), 0.f);
            float t2 = fmaxf(fmaf(g_Aa[4*i+2], y.z, g_Ca[4*i+2]), 0.f);
            float t3 = fmaxf(fmaf(g_Aa[4*i+3], y.w, g_Ca[4*i+3]), 0.f);
            float s0 = 1.0f / (1.0f + expf(-t0));
            float s1 = 1.0f / (1.0f + expf(-t1));
            float s2 = 1.0f / (1.0f + expf(-t2));
            float s3 = 1.0f / (1.0f + expf(-t3));
            xc[4*u+0] = fmaf(a.x, s0, a.x);
            xc[4*u+1] = fmaf(a.y, s1, a.y);
            xc[4*u+2] = fmaf(a.z, s2, a.z);
            xc[4*u+3] = fmaf(a.w, s3, a.w);
        }
#pragma unroll
        for (int j = 0; j < 16; ++j) {
            const int k = kk*16 + j;
            const float xs = xc[j];
#pragma unroll
            for (int g = 0; g < 8; ++g) {
                const float4 w = W4[k*8+g];
                acc[g].x = fmaf(xs, w.x, acc[g].x);
                acc[g].y = fmaf(xs, w.y, acc[g].y);
                acc[g].z = fmaf(xs, w.z, acc[g].z);
                acc[g].w = fmaf(xs, w.w, acc[g].w);
            }
        }
    }

    const int warp = tid >> 5, lane = tid & 31;
    float4* yp = (float4*)(g_Y2 + (size_t)r * COUT + cg*32);
#pragma unroll
    for (int g = 0; g < 8; ++g) {
        yp[g] = acc[g];
        const float vs[4] = {acc[g].x, acc[g].y, acc[g].z, acc[g].w};
#pragma unroll
        for (int u = 0; u < 4; ++u) {
            const float s = warp_sum(vs[u]);
            const float qq = warp_sum(vs[u]*vs[u]);
            if (lane == 0) { wsum[warp][4*g+u] = s; wsq[warp][4*g+u] = qq; }
        }
    }
    __syncthreads();
    if (tid < 32) {
        g_Ps2[blockIdx.x*COUT + cg*32 + tid] = wsum[0][tid]+wsum[1][tid]+wsum[2][tid]+wsum[3][tid];
        g_Pq2[blockIdx.x*COUT + cg*32 + tid] = wsq [0][tid]+wsq [1][tid]+wsq [2][tid]+wsq [3][tid];
    }
}

// ---------------- final ----------------
__global__ void __launch_bounds__(256) k_final(float* __restrict__ out)
{
    const int i = blockIdx.x * 256 + threadIdx.x;
    const int c = i & (COUT-1);
    out[i] = fmaxf(fmaf(g_A2[c], g_Y2[i], g_C2[c]), 0.f);
}

// ---------------- launch ----------------
extern "C" void kernel_launch(void* const* d_in, const int* in_sizes, int n_in,
                              void* d_out, int out_size)
{
    const float* coords = (const float*)d_in[0];
    const float* feats  = (const float*)d_in[1];
    const float* W1  = (const float*)d_in[3];
    const float* b1  = (const float*)d_in[4];
    const float* g1  = (const float*)d_in[5];
    const float* be1 = (const float*)d_in[6];
    const float* Wa  = (const float*)d_in[7];
    const float* ba  = (const float*)d_in[8];
    const float* ga  = (const float*)d_in[9];
    const float* bea = (const float*)d_in[10];
    const float* W2  = (const float*)d_in[11];
    const float* b2  = (const float*)d_in[12];
    const float* g2  = (const float*)d_in[13];
    const float* be2 = (const float*)d_in[14];
    float* out = (float*)d_out;

    k_prep  <<<ROWS/256, 256>>>(coords);
    k_knn   <<<dim3(NN/16, BB), 256>>>();
    k_gather<<<ROWS/8, 256>>>(feats);
    k_mlp1  <<<dim3(256, 4), 128>>>(W1, b1);   // launch #4 -> profiled
    k_stats1<<<1, 256>>>(g1, be1);
    k_mlpa  <<<dim3(256, 4), 128>>>(Wa, ba);
    k_statsa<<<1, 256>>>(ga, bea);
    k_mlp2  <<<dim3(256, 4), 128>>>(W2, b2);
    k_stats2<<<1, 512>>>(g2, be2);
    k_final <<<(ROWS*COUT)/256, 256>>>(out);
}